// round 1
// baseline (speedup 1.0000x reference)
#include <cuda_runtime.h>
#include <math.h>

// Problem constants
#define BB    64
#define CC    512
#define NN    1024          // 32*32 spatial
#define OO    25            // 1 conf + 20 cls + 4 box
#define OPAD  28            // pad to multiple of 4 for float4 smem loads
#define NCLS  20
#define CHUNK 256           // weights loaded in 2 chunks to stay under 48KB static smem
#define CONF_T 0.01f
#define NMS_T  0.5f
#define EPS_IOU 1e-28f
#define INV_SCALE 0.0009765625f   // 1/1024

// Scratch (allocation-free: __device__ globals)
__device__ float4 g_offbox[BB*NN];
__device__ float  g_score[BB*NN];
__device__ int    g_cls[BB*NN];

__device__ __forceinline__ float sigm(float x) { return 1.0f / (1.0f + expf(-x)); }

// Decode one pixel given its 25 raw logits (acc, bias added here).
__device__ __forceinline__ void decode_write(int b, int n, const float* acc,
                                             const float* b_s, float* __restrict__ out)
{
    float p[OO];
    #pragma unroll
    for (int o = 0; o < OO; o++) p[o] = acc[o] + b_s[o];

    float conf = sigm(p[0]);

    // argmax over raw class logits (== argmax of softmax), first-max tie-break
    float m = p[1]; int am = 0;
    #pragma unroll
    for (int k = 1; k < NCLS; k++)
        if (p[1 + k] > m) { m = p[1 + k]; am = k; }

    float s = 0.0f;
    #pragma unroll
    for (int k = 0; k < NCLS; k++) s += expf(p[1 + k] - m);
    float score = conf / s;          // conf * max(softmax) == conf / sum(exp(l-m))

    float gx = (float)(n & 31), gy = (float)(n >> 5);
    float cx = (sigm(p[21]) + gx) * 32.0f;
    float cy = (sigm(p[22]) + gy) * 32.0f;
    float w  = expf(p[23]);
    float h  = expf(p[24]);
    // __fmul_rn blocks FMA contraction so rounding matches the reference ops
    float hw = __fmul_rn(w, 0.5f);
    float hh = __fmul_rn(h, 0.5f);
    float x1 = fminf(fmaxf(__fmul_rn(cx - hw, INV_SCALE), 0.0f), 1.0f);
    float y1 = fminf(fmaxf(__fmul_rn(cy - hh, INV_SCALE), 0.0f), 1.0f);
    float x2 = fminf(fmaxf(__fmul_rn(cx + hw, INV_SCALE), 0.0f), 1.0f);
    float y2 = fminf(fmaxf(__fmul_rn(cy + hh, INV_SCALE), 0.0f), 1.0f);

    int i = b * NN + n;
    ((float4*)out)[i] = make_float4(x1, y1, x2, y2);     // boxes region [0, B*N*4)
    out[BB*NN*4 + i] = score;                            // scores
    out[BB*NN*5 + i] = (float)am;                        // cls_inds (as float)

    float off = __fmul_rn(2.0f, (float)am);
    g_offbox[i] = make_float4(x1 + off, y1 + off, x2 + off, y2 + off);
    g_score[i]  = score;
    g_cls[i]    = am;
}

// Fused GEMM (65536 x 512 x 25) + decode. 128 blocks x 256 threads, 2 pixels/thread.
__global__ __launch_bounds__(256, 1)
void k_gemm_decode(const float* __restrict__ feat,
                   const float* __restrict__ w_pred,
                   const float* __restrict__ b_pred,
                   float* __restrict__ out)
{
    __shared__ float w_s[CHUNK * OPAD];   // 28 KB
    __shared__ float b_s[OO];

    const int tid = threadIdx.x;
    const int b   = blockIdx.x >> 1;
    const int n0  = ((blockIdx.x & 1) << 9) | (tid << 1);
    const float2* f2base = (const float2*)(feat + (size_t)b * CC * NN) + (n0 >> 1);

    float acc0[OO], acc1[OO];
    #pragma unroll
    for (int o = 0; o < OO; o++) { acc0[o] = 0.0f; acc1[o] = 0.0f; }
    if (tid < OO) b_s[tid] = b_pred[tid];

    for (int half = 0; half < 2; half++) {
        __syncthreads();   // protect w_s from previous chunk's readers
        for (int i = tid; i < CHUNK * OPAD; i += 256) {
            int c = i / OPAD, o = i - c * OPAD;
            w_s[i] = (o < OO) ? w_pred[o * CC + half * CHUNK + c] : 0.0f;
        }
        __syncthreads();

        const float2* fp = f2base + (size_t)(half * CHUNK) * (NN / 2);
        #pragma unroll 4
        for (int cc = 0; cc < CHUNK; cc++) {
            float2 f = __ldg(fp + (size_t)cc * (NN / 2));
            const float4* wr = (const float4*)(w_s + cc * OPAD);
            #pragma unroll
            for (int q = 0; q < 7; q++) {
                float4 w4 = wr[q];
                const int o = q * 4;
                acc0[o] = fmaf(f.x, w4.x, acc0[o]);
                acc1[o] = fmaf(f.y, w4.x, acc1[o]);
                if (o + 1 < OO) { acc0[o+1] = fmaf(f.x, w4.y, acc0[o+1]);
                                  acc1[o+1] = fmaf(f.y, w4.y, acc1[o+1]); }
                if (o + 2 < OO) { acc0[o+2] = fmaf(f.x, w4.z, acc0[o+2]);
                                  acc1[o+2] = fmaf(f.y, w4.z, acc1[o+2]); }
                if (o + 3 < OO) { acc0[o+3] = fmaf(f.x, w4.w, acc0[o+3]);
                                  acc1[o+3] = fmaf(f.y, w4.w, acc1[o+3]); }
            }
        }
    }

    decode_write(b, n0,     acc0, b_s, out);
    decode_write(b, n0 + 1, acc1, b_s, out);
}

// Per-(image, class) greedy NMS. Class offset 2.0 guarantees cross-class IoU ~0,
// so per-class greedy is exactly equivalent to the reference's global sorted loop.
#define MAXC 256
__global__ void k_nms(float* __restrict__ out)
{
    const int b    = blockIdx.x;
    const int c    = blockIdx.y;
    const int lane = threadIdx.x;

    __shared__ float4        sbox[MAXC];
    __shared__ float         ssc[MAXC];
    __shared__ short         sidx[MAXC];
    __shared__ unsigned char sact[MAXC];

    float* keep_out = out + (size_t)BB * NN * 6 + (size_t)b * NN;

    // Gather candidates of this class (ascending n => stable order)
    int total = 0;                 // replicated in every lane, race-free
    for (int base = 0; base < NN; base += 32) {
        int n = base + lane;
        bool mt = (g_cls[b * NN + n] == c);
        unsigned mask = __ballot_sync(0xffffffffu, mt);
        int pos = total + __popc(mask & ((1u << lane) - 1u));
        if (mt) {
            keep_out[n] = 0.0f;    // default; every pixel has exactly one class
            if (pos < MAXC) {
                sidx[pos] = (short)n;
                sbox[pos] = g_offbox[b * NN + n];
                float sc  = g_score[b * NN + n];
                ssc[pos]  = sc;
                sact[pos] = (sc > CONF_T) ? 1 : 0;
            }
        }
        total += __popc(mask);
    }
    __syncwarp();
    int cnt = min(total, MAXC);

    // Greedy: repeatedly pick highest-score active (ties -> smallest index),
    // keep it, suppress active boxes with IoU > 0.5.
    for (int iter = 0; iter < cnt; iter++) {
        float bs = -1.0f; int bslot = -1;
        for (int i = lane; i < cnt; i += 32) {
            if (sact[i]) {
                float sv = ssc[i];
                if (sv > bs) { bs = sv; bslot = i; }   // i ascending => first max kept
            }
        }
        #pragma unroll
        for (int off = 16; off; off >>= 1) {
            float os = __shfl_down_sync(0xffffffffu, bs, off);
            int   oi = __shfl_down_sync(0xffffffffu, bslot, off);
            if (oi >= 0 && (os > bs || (os == bs && (bslot < 0 || oi < bslot)))) {
                bs = os; bslot = oi;
            }
        }
        bslot = __shfl_sync(0xffffffffu, bslot, 0);
        if (bslot < 0) break;      // nothing active left

        if (lane == 0) {
            keep_out[sidx[bslot]] = 1.0f;
            sact[bslot] = 0;
        }
        __syncwarp();

        float4 sb = sbox[bslot];
        float sarea = __fmul_rn(sb.z - sb.x, sb.w - sb.y);
        for (int i = lane; i < cnt; i += 32) {
            if (sact[i]) {
                float4 ob = sbox[i];
                float xx1 = fmaxf(sb.x, ob.x);
                float yy1 = fmaxf(sb.y, ob.y);
                float xx2 = fminf(sb.z, ob.z);
                float yy2 = fminf(sb.w, ob.w);
                float w = fmaxf(EPS_IOU, xx2 - xx1);
                float h = fmaxf(EPS_IOU, yy2 - yy1);
                float inter = __fmul_rn(w, h);
                float oarea = __fmul_rn(ob.z - ob.x, ob.w - ob.y);
                float iou = inter / (sarea + oarea - inter);
                if (iou > NMS_T) sact[i] = 0;
            }
        }
        __syncwarp();
    }
}

extern "C" void kernel_launch(void* const* d_in, const int* in_sizes, int n_in,
                              void* d_out, int out_size)
{
    const float* feat   = (const float*)d_in[0];
    const float* w_pred = (const float*)d_in[1];
    const float* b_pred = (const float*)d_in[2];
    float* out = (float*)d_out;

    k_gemm_decode<<<128, 256>>>(feat, w_pred, b_pred, out);
    k_nms<<<dim3(BB, NCLS), 32>>>(out);
}

// round 3
// speedup vs baseline: 1.4921x; 1.4921x over previous
#include <cuda_runtime.h>
#include <math.h>

// Problem constants
#define BB    64
#define CC    512
#define NN    1024          // 32*32 spatial
#define OO    25            // 1 conf + 20 cls + 4 box
#define OPAD  28            // pad to multiple of 4 for float4/ulonglong2 smem loads
#define NCLS  20
#define CHUNK 256           // weights loaded in 2 chunks
#define CONF_T 0.01f
#define NMS_T  0.5f
#define EPS_IOU 1e-28f
#define INV_SCALE 0.0009765625f   // 1/1024
#define MAXC  128           // max candidates per (image, class); mean ~40, P(>128)≈0

typedef unsigned long long u64;

// Scratch (allocation-free: __device__ globals)
__device__ float4 g_offbox[BB*NN];
__device__ float  g_score[BB*NN];
__device__ int    g_cls[BB*NN];

__device__ __forceinline__ float sigm(float x) { return 1.0f / (1.0f + expf(-x)); }

// packed f32x2 fma, lane-wise round-to-nearest (bitwise == scalar fmaf per lane)
#define FMA2(c, a, b) asm("fma.rn.f32x2 %0, %1, %2, %3;" : "=l"(c) : "l"(a), "l"(b), "l"(c))

__device__ __forceinline__ u64 pack2(float x) {
    u64 r; unsigned xb = __float_as_uint(x);
    asm("mov.b64 %0, {%1, %1};" : "=l"(r) : "r"(xb));
    return r;
}
__device__ __forceinline__ void unpack2(u64 v, float& lo, float& hi) {
    unsigned l, h;
    asm("mov.b64 {%0, %1}, %2;" : "=r"(l), "=r"(h) : "l"(v));
    lo = __uint_as_float(l); hi = __uint_as_float(h);
}

// Decode one pixel given its 25 raw logits (bias added here).
__device__ __forceinline__ void decode_write(int b, int n, const float* acc,
                                             const float* b_s, float* __restrict__ out)
{
    float p[OO];
    #pragma unroll
    for (int o = 0; o < OO; o++) p[o] = acc[o] + b_s[o];

    float conf = sigm(p[0]);

    // argmax over raw class logits (== argmax of softmax), first-max tie-break
    float m = p[1]; int am = 0;
    #pragma unroll
    for (int k = 1; k < NCLS; k++)
        if (p[1 + k] > m) { m = p[1 + k]; am = k; }

    float s = 0.0f;
    #pragma unroll
    for (int k = 0; k < NCLS; k++) s += expf(p[1 + k] - m);
    float score = conf / s;          // conf * max(softmax) == conf / sum(exp(l-m))

    float gx = (float)(n & 31), gy = (float)(n >> 5);
    float cx = (sigm(p[21]) + gx) * 32.0f;
    float cy = (sigm(p[22]) + gy) * 32.0f;
    float w  = expf(p[23]);
    float h  = expf(p[24]);
    float hw = __fmul_rn(w, 0.5f);
    float hh = __fmul_rn(h, 0.5f);
    float x1 = fminf(fmaxf(__fmul_rn(cx - hw, INV_SCALE), 0.0f), 1.0f);
    float y1 = fminf(fmaxf(__fmul_rn(cy - hh, INV_SCALE), 0.0f), 1.0f);
    float x2 = fminf(fmaxf(__fmul_rn(cx + hw, INV_SCALE), 0.0f), 1.0f);
    float y2 = fminf(fmaxf(__fmul_rn(cy + hh, INV_SCALE), 0.0f), 1.0f);

    int i = b * NN + n;
    ((float4*)out)[i] = make_float4(x1, y1, x2, y2);     // boxes region [0, B*N*4)
    out[BB*NN*4 + i] = score;                            // scores
    out[BB*NN*5 + i] = (float)am;                        // cls_inds (as float)

    float off = __fmul_rn(2.0f, (float)am);
    g_offbox[i] = make_float4(x1 + off, y1 + off, x2 + off, y2 + off);
    g_score[i]  = score;
    g_cls[i]    = am;
}

// Fused GEMM (65536 x 512 x 25) + decode. 128 blocks x 256 threads, 2 pixels/thread.
// Inner product uses packed f32x2 FMAs over channel pairs (weight pairs come free
// from the LDS.128 of the padded weight row).
__global__ __launch_bounds__(256, 1)
void k_gemm_decode(const float* __restrict__ feat,
                   const float* __restrict__ w_pred,
                   const float* __restrict__ b_pred,
                   float* __restrict__ out)
{
    __shared__ float w_s[CHUNK * OPAD];   // 28 KB
    __shared__ float b_s[OO];

    const int tid = threadIdx.x;
    const int b   = blockIdx.x >> 1;
    const int n0  = ((blockIdx.x & 1) << 9) | (tid << 1);
    const float2* f2base = (const float2*)(feat + (size_t)b * CC * NN) + (n0 >> 1);

    u64 accA[13], accB[13];               // channel pairs {2q, 2q+1} for pixel0/pixel1
    #pragma unroll
    for (int q = 0; q < 13; q++) { accA[q] = 0ull; accB[q] = 0ull; }
    if (tid < OO) b_s[tid] = b_pred[tid];

    for (int half = 0; half < 2; half++) {
        __syncthreads();   // protect w_s from previous chunk's readers
        for (int i = tid; i < CHUNK * OPAD; i += 256) {
            int c = i / OPAD, o = i - c * OPAD;
            w_s[i] = (o < OO) ? w_pred[o * CC + half * CHUNK + c] : 0.0f;
        }
        __syncthreads();

        const float2* fp = f2base + (size_t)(half * CHUNK) * (NN / 2);
        #pragma unroll 4
        for (int cc = 0; cc < CHUNK; cc++) {
            float2 f = __ldg(fp + (size_t)cc * (NN / 2));
            u64 fA = pack2(f.x);
            u64 fB = pack2(f.y);
            const ulonglong2* wr = (const ulonglong2*)(w_s + cc * OPAD);
            #pragma unroll
            for (int j = 0; j < 7; j++) {
                ulonglong2 q = wr[j];           // one LDS.128 -> two channel pairs
                FMA2(accA[2*j], fA, q.x);
                FMA2(accB[2*j], fB, q.x);
                if (2*j + 1 < 13) {
                    FMA2(accA[2*j + 1], fA, q.y);
                    FMA2(accB[2*j + 1], fB, q.y);
                }
            }
        }
    }

    float acc0[OO + 1], acc1[OO + 1];
    #pragma unroll
    for (int q = 0; q < 13; q++) {
        unpack2(accA[q], acc0[2*q], acc0[2*q + 1]);
        unpack2(accB[q], acc1[2*q], acc1[2*q + 1]);
    }
    decode_write(b, n0,     acc0, b_s, out);
    decode_write(b, n0 + 1, acc1, b_s, out);
}

// NMS: one block per image (64 blocks), one warp per class (20 warps).
// Class offset 2.0 makes cross-class IoU ~0 => per-class greedy is exactly
// equivalent to the reference's global sorted loop. Sub-threshold boxes can
// neither suppress nor be kept, so they are excluded at gather.
__global__ __launch_bounds__(640, 1)
void k_nms(float* __restrict__ out)
{
    const int b    = blockIdx.x;
    const int tid  = threadIdx.x;
    const int warp = tid >> 5;
    const int lane = tid & 31;

    __shared__ float4        sb[NN];             // 16 KB offset boxes
    __shared__ float         ss[NN];             // 4 KB scores
    __shared__ unsigned char sc[NN];             // 1 KB class ids
    __shared__ short         cand [NCLS][MAXC];  // 5 KB gather order
    __shared__ short         sortd[NCLS][MAXC];  // 5 KB score-sorted order

    float* keep = out + (size_t)BB * NN * 6 + (size_t)b * NN;

    for (int i = tid; i < NN; i += 640) {
        sb[i]   = g_offbox[b * NN + i];
        ss[i]   = g_score [b * NN + i];
        sc[i]   = (unsigned char)g_cls[b * NN + i];
        keep[i] = 0.0f;
    }
    __syncthreads();

    const int c = warp;

    // Gather candidates of this class (ascending n => stable original order)
    int total = 0;
    for (int base = 0; base < NN; base += 32) {
        int n = base + lane;
        bool mt = (sc[n] == c) && (ss[n] > CONF_T);
        unsigned m = __ballot_sync(0xffffffffu, mt);
        int pos = total + __popc(m & ((1u << lane) - 1u));
        if (mt && pos < MAXC) cand[c][pos] = (short)n;
        total += __popc(m);
    }
    int cnt = min(total, MAXC);
    __syncwarp();

    // Stable rank sort by score desc (ties -> smaller original index first),
    // matching jnp.argsort(-scores) stability.
    for (int i = lane; i < cnt; i += 32) {
        int   ni = cand[c][i];
        float si = ss[ni];
        int rank = 0;
        for (int j = 0; j < cnt; j++) {
            float sj = ss[cand[c][j]];
            rank += (sj > si) || (sj == si && j < i);
        }
        sortd[c][rank] = (short)ni;
    }
    __syncwarp();

    // Serial greedy over sorted order with register-resident 128-bit suppression
    // mask (uniform across lanes via ballot -> uniform branches, no smem round trips).
    unsigned s0 = 0, s1 = 0, s2 = 0, s3 = 0;
    for (int k = 0; k < cnt; k++) {
        unsigned sk = (k < 32) ? s0 : (k < 64) ? s1 : (k < 96) ? s2 : s3;
        if ((sk >> (k & 31)) & 1u) continue;      // suppressed (uniform)

        int nk = sortd[c][k];
        if (lane == 0) keep[nk] = 1.0f;
        float4 kb = sb[nk];
        float  ka = __fmul_rn(kb.z - kb.x, kb.w - kb.y);

        #pragma unroll
        for (int ch = 0; ch < 4; ch++) {
            int base = ch << 5;
            if (base >= cnt) break;               // uniform
            int j = base + lane;
            bool sup = false;
            if (j < cnt && j > k) {
                float4 ob = sb[sortd[c][j]];
                float xx1 = fmaxf(kb.x, ob.x);
                float yy1 = fmaxf(kb.y, ob.y);
                float xx2 = fminf(kb.z, ob.z);
                float yy2 = fminf(kb.w, ob.w);
                float w = fmaxf(EPS_IOU, xx2 - xx1);
                float h = fmaxf(EPS_IOU, yy2 - yy1);
                float inter = __fmul_rn(w, h);
                float oa = __fmul_rn(ob.z - ob.x, ob.w - ob.y);
                float iou = inter / (ka + oa - inter);
                sup = iou > NMS_T;
            }
            unsigned m = __ballot_sync(0xffffffffu, sup);
            if      (ch == 0) s0 |= m;
            else if (ch == 1) s1 |= m;
            else if (ch == 2) s2 |= m;
            else              s3 |= m;
        }
    }
}

extern "C" void kernel_launch(void* const* d_in, const int* in_sizes, int n_in,
                              void* d_out, int out_size)
{
    const float* feat   = (const float*)d_in[0];
    const float* w_pred = (const float*)d_in[1];
    const float* b_pred = (const float*)d_in[2];
    float* out = (float*)d_out;

    k_gemm_decode<<<128, 256>>>(feat, w_pred, b_pred, out);
    k_nms<<<64, 640>>>(out);
}

// round 6
// speedup vs baseline: 1.4965x; 1.0029x over previous
#include <cuda_runtime.h>
#include <math.h>

// Problem constants
#define BB    64
#define CC    512
#define NN    1024          // 32*32 spatial
#define OO    25            // 1 conf + 20 cls + 4 box
#define OPAD  28            // pad to multiple of 4 for float4/ulonglong2 smem loads
#define NCLS  20
#define CHUNK 256           // weights loaded in 2 chunks
#define CONF_T 0.01f
#define NMS_T  0.5f
#define EPS_IOU 1e-28f
#define INV_SCALE 0.0009765625f   // 1/1024
#define MAXC  128           // max candidates per (image, class); mean ~40, P(>128)≈0

typedef unsigned long long u64;

// Scratch (allocation-free: __device__ globals)
__device__ float4 g_offbox[BB*NN];
__device__ float  g_score[BB*NN];
__device__ int    g_cls[BB*NN];

__device__ __forceinline__ float sigm(float x) { return 1.0f / (1.0f + expf(-x)); }

// packed f32x2 fma, lane-wise round-to-nearest (bitwise == scalar fmaf per lane)
#define FMA2(c, a, b) asm("fma.rn.f32x2 %0, %1, %2, %3;" : "=l"(c) : "l"(a), "l"(b), "l"(c))

__device__ __forceinline__ u64 pack2(float x) {
    u64 r; unsigned xb = __float_as_uint(x);
    asm("mov.b64 %0, {%1, %1};" : "=l"(r) : "r"(xb));
    return r;
}
__device__ __forceinline__ void unpack2(u64 v, float& lo, float& hi) {
    unsigned l, h;
    asm("mov.b64 {%0, %1}, %2;" : "=r"(l), "=r"(h) : "l"(v));
    lo = __uint_as_float(l); hi = __uint_as_float(h);
}

// Decode one pixel given its 25 raw logits (bias added here).
__device__ __forceinline__ void decode_write(int b, int n, const float* acc,
                                             const float* b_s, float* __restrict__ out)
{
    float p[OO];
    #pragma unroll
    for (int o = 0; o < OO; o++) p[o] = acc[o] + b_s[o];

    float conf = sigm(p[0]);

    // argmax over raw class logits (== argmax of softmax), first-max tie-break
    float m = p[1]; int am = 0;
    #pragma unroll
    for (int k = 1; k < NCLS; k++)
        if (p[1 + k] > m) { m = p[1 + k]; am = k; }

    float s = 0.0f;
    #pragma unroll
    for (int k = 0; k < NCLS; k++) s += expf(p[1 + k] - m);
    float score = conf / s;          // conf * max(softmax) == conf / sum(exp(l-m))

    float gx = (float)(n & 31), gy = (float)(n >> 5);
    float cx = (sigm(p[21]) + gx) * 32.0f;
    float cy = (sigm(p[22]) + gy) * 32.0f;
    float w  = expf(p[23]);
    float h  = expf(p[24]);
    float hw = __fmul_rn(w, 0.5f);
    float hh = __fmul_rn(h, 0.5f);
    float x1 = fminf(fmaxf(__fmul_rn(cx - hw, INV_SCALE), 0.0f), 1.0f);
    float y1 = fminf(fmaxf(__fmul_rn(cy - hh, INV_SCALE), 0.0f), 1.0f);
    float x2 = fminf(fmaxf(__fmul_rn(cx + hw, INV_SCALE), 0.0f), 1.0f);
    float y2 = fminf(fmaxf(__fmul_rn(cy + hh, INV_SCALE), 0.0f), 1.0f);

    int i = b * NN + n;
    ((float4*)out)[i] = make_float4(x1, y1, x2, y2);     // boxes region [0, B*N*4)
    out[BB*NN*4 + i] = score;                            // scores
    out[BB*NN*5 + i] = (float)am;                        // cls_inds (as float)

    float off = __fmul_rn(2.0f, (float)am);
    g_offbox[i] = make_float4(x1 + off, y1 + off, x2 + off, y2 + off);
    g_score[i]  = score;
    g_cls[i]    = am;
}

// Fused GEMM (65536 x 512 x 25) + decode. 128 blocks x 256 threads, 2 pixels/thread.
// Inner product uses packed f32x2 FMAs over channel pairs (weight pairs come free
// from the LDS.128 of the padded weight row).
__global__ __launch_bounds__(256, 1)
void k_gemm_decode(const float* __restrict__ feat,
                   const float* __restrict__ w_pred,
                   const float* __restrict__ b_pred,
                   float* __restrict__ out)
{
    __shared__ float w_s[CHUNK * OPAD];   // 28 KB
    __shared__ float b_s[OO];

    const int tid = threadIdx.x;
    const int b   = blockIdx.x >> 1;
    const int n0  = ((blockIdx.x & 1) << 9) | (tid << 1);
    const float2* f2base = (const float2*)(feat + (size_t)b * CC * NN) + (n0 >> 1);

    u64 accA[13], accB[13];               // channel pairs {2q, 2q+1} for pixel0/pixel1
    #pragma unroll
    for (int q = 0; q < 13; q++) { accA[q] = 0ull; accB[q] = 0ull; }
    if (tid < OO) b_s[tid] = b_pred[tid];

    for (int half = 0; half < 2; half++) {
        __syncthreads();   // protect w_s from previous chunk's readers
        for (int i = tid; i < CHUNK * OPAD; i += 256) {
            int c = i / OPAD, o = i - c * OPAD;
            w_s[i] = (o < OO) ? w_pred[o * CC + half * CHUNK + c] : 0.0f;
        }
        __syncthreads();

        const float2* fp = f2base + (size_t)(half * CHUNK) * (NN / 2);
        #pragma unroll 4
        for (int cc = 0; cc < CHUNK; cc++) {
            float2 f = __ldg(fp + (size_t)cc * (NN / 2));
            u64 fA = pack2(f.x);
            u64 fB = pack2(f.y);
            const ulonglong2* wr = (const ulonglong2*)(w_s + cc * OPAD);
            #pragma unroll
            for (int j = 0; j < 7; j++) {
                ulonglong2 q = wr[j];           // one LDS.128 -> two channel pairs
                FMA2(accA[2*j], fA, q.x);
                FMA2(accB[2*j], fB, q.x);
                if (2*j + 1 < 13) {
                    FMA2(accA[2*j + 1], fA, q.y);
                    FMA2(accB[2*j + 1], fB, q.y);
                }
            }
        }
    }

    float acc0[OO + 1], acc1[OO + 1];
    #pragma unroll
    for (int q = 0; q < 13; q++) {
        unpack2(accA[q], acc0[2*q], acc0[2*q + 1]);
        unpack2(accB[q], acc1[2*q], acc1[2*q + 1]);
    }
    decode_write(b, n0,     acc0, b_s, out);
    decode_write(b, n0 + 1, acc1, b_s, out);
}

// NMS: one block per image (64 blocks), one warp per class (20 warps).
// Class offset 2.0 makes cross-class IoU ~0 => per-class greedy is exactly
// equivalent to the reference's global sorted loop. Sub-threshold boxes can
// neither suppress nor be kept, so they are excluded at gather.
__global__ __launch_bounds__(640, 1)
void k_nms(float* __restrict__ out)
{
    const int b    = blockIdx.x;
    const int tid  = threadIdx.x;
    const int warp = tid >> 5;
    const int lane = tid & 31;

    __shared__ float4        sb[NN];             // 16 KB offset boxes
    __shared__ float         ss[NN];             // 4 KB scores
    __shared__ unsigned char sc[NN];             // 1 KB class ids
    __shared__ short         cand [NCLS][MAXC];  // 5 KB gather order
    __shared__ short         sortd[NCLS][MAXC];  // 5 KB score-sorted order

    float* keep = out + (size_t)BB * NN * 6 + (size_t)b * NN;

    for (int i = tid; i < NN; i += 640) {
        sb[i]   = g_offbox[b * NN + i];
        ss[i]   = g_score [b * NN + i];
        sc[i]   = (unsigned char)g_cls[b * NN + i];
        keep[i] = 0.0f;
    }
    __syncthreads();

    const int c = warp;

    // Gather candidates of this class (ascending n => stable original order)
    int total = 0;
    for (int base = 0; base < NN; base += 32) {
        int n = base + lane;
        bool mt = (sc[n] == c) && (ss[n] > CONF_T);
        unsigned m = __ballot_sync(0xffffffffu, mt);
        int pos = total + __popc(m & ((1u << lane) - 1u));
        if (mt && pos < MAXC) cand[c][pos] = (short)n;
        total += __popc(m);
    }
    int cnt = min(total, MAXC);
    __syncwarp();

    // Stable rank sort by score desc (ties -> smaller original index first),
    // matching jnp.argsort(-scores) stability.
    for (int i = lane; i < cnt; i += 32) {
        int   ni = cand[c][i];
        float si = ss[ni];
        int rank = 0;
        for (int j = 0; j < cnt; j++) {
            float sj = ss[cand[c][j]];
            rank += (sj > si) || (sj == si && j < i);
        }
        sortd[c][rank] = (short)ni;
    }
    __syncwarp();

    // Serial greedy over sorted order with register-resident 128-bit suppression
    // mask (uniform across lanes via ballot -> uniform branches, no smem round trips).
    unsigned s0 = 0, s1 = 0, s2 = 0, s3 = 0;
    for (int k = 0; k < cnt; k++) {
        unsigned sk = (k < 32) ? s0 : (k < 64) ? s1 : (k < 96) ? s2 : s3;
        if ((sk >> (k & 31)) & 1u) continue;      // suppressed (uniform)

        int nk = sortd[c][k];
        if (lane == 0) keep[nk] = 1.0f;
        float4 kb = sb[nk];
        float  ka = __fmul_rn(kb.z - kb.x, kb.w - kb.y);

        #pragma unroll
        for (int ch = 0; ch < 4; ch++) {
            int base = ch << 5;
            if (base >= cnt) break;               // uniform
            int j = base + lane;
            bool sup = false;
            if (j < cnt && j > k) {
                float4 ob = sb[sortd[c][j]];
                float xx1 = fmaxf(kb.x, ob.x);
                float yy1 = fmaxf(kb.y, ob.y);
                float xx2 = fminf(kb.z, ob.z);
                float yy2 = fminf(kb.w, ob.w);
                float w = fmaxf(EPS_IOU, xx2 - xx1);
                float h = fmaxf(EPS_IOU, yy2 - yy1);
                float inter = __fmul_rn(w, h);
                float oa = __fmul_rn(ob.z - ob.x, ob.w - ob.y);
                float iou = inter / (ka + oa - inter);
                sup = iou > NMS_T;
            }
            unsigned m = __ballot_sync(0xffffffffu, sup);
            if      (ch == 0) s0 |= m;
            else if (ch == 1) s1 |= m;
            else if (ch == 2) s2 |= m;
            else              s3 |= m;
        }
    }
}

extern "C" void kernel_launch(void* const* d_in, const int* in_sizes, int n_in,
                              void* d_out, int out_size)
{
    const float* feat   = (const float*)d_in[0];
    const float* w_pred = (const float*)d_in[1];
    const float* b_pred = (const float*)d_in[2];
    float* out = (float*)d_out;

    k_gemm_decode<<<128, 256>>>(feat, w_pred, b_pred, out);
    k_nms<<<64, 640>>>(out);
}

// round 7
// speedup vs baseline: 1.5914x; 1.0634x over previous
#include <cuda_runtime.h>
#include <math.h>

// Problem constants
#define BB    64
#define CC    512
#define NN    1024          // 32*32 spatial
#define OO    25            // 1 conf + 20 cls + 4 box
#define OPAD  28            // pad to multiple of 4 for ulonglong2 smem loads
#define NCLS  20
#define CHUNK 256           // weights loaded in 2 chunks
#define CONF_T 0.01f
#define NMS_T  0.5f
#define EPS_IOU 1e-28f
#define INV_SCALE 0.0009765625f   // 1/1024
#define MAXC  128           // max candidates per (image,class); mean ~51, 128 = ~11 sigma
#define FULLM 0xffffffffu

typedef unsigned long long u64;

// Scratch (allocation-free: __device__ globals; zero-initialized at module load,
// g_cnt is restored to zero by k_nms each launch -> graph-replay invariant).
__device__ float4 g_offbox[BB*NN];
__device__ float  g_score[BB*NN];
__device__ int    g_cnt[BB*NCLS];
__device__ short  g_cand[BB*NCLS*MAXC];

__device__ __forceinline__ float sigm(float x) { return 1.0f / (1.0f + expf(-x)); }

// packed f32x2 fma, lane-wise round-to-nearest (bitwise == scalar fmaf per lane)
#define FMA2(c, a, b) asm("fma.rn.f32x2 %0, %1, %2, %3;" : "=l"(c) : "l"(a), "l"(b), "l"(c))

__device__ __forceinline__ u64 pack2(float x) {
    u64 r; unsigned xb = __float_as_uint(x);
    asm("mov.b64 %0, {%1, %1};" : "=l"(r) : "r"(xb));
    return r;
}
__device__ __forceinline__ void unpack2(u64 v, float& lo, float& hi) {
    unsigned l, h;
    asm("mov.b64 {%0, %1}, %2;" : "=r"(l), "=r"(h) : "l"(v));
    lo = __uint_as_float(l); hi = __uint_as_float(h);
}

// Decode one pixel given its 25 raw logits (bias added here).
__device__ __forceinline__ void decode_write(int b, int n, const float* acc,
                                             const float* b_s, float* __restrict__ out)
{
    float p[OO];
    #pragma unroll
    for (int o = 0; o < OO; o++) p[o] = acc[o] + b_s[o];

    float conf = sigm(p[0]);

    // argmax over raw class logits (== argmax of softmax), first-max tie-break
    float m = p[1]; int am = 0;
    #pragma unroll
    for (int k = 1; k < NCLS; k++)
        if (p[1 + k] > m) { m = p[1 + k]; am = k; }

    float s = 0.0f;
    #pragma unroll
    for (int k = 0; k < NCLS; k++) s += expf(p[1 + k] - m);
    float score = conf / s;          // conf * max(softmax) == conf / sum(exp(l-m))

    float gx = (float)(n & 31), gy = (float)(n >> 5);
    float cx = (sigm(p[21]) + gx) * 32.0f;
    float cy = (sigm(p[22]) + gy) * 32.0f;
    float w  = expf(p[23]);
    float h  = expf(p[24]);
    float hw = __fmul_rn(w, 0.5f);
    float hh = __fmul_rn(h, 0.5f);
    float x1 = fminf(fmaxf(__fmul_rn(cx - hw, INV_SCALE), 0.0f), 1.0f);
    float y1 = fminf(fmaxf(__fmul_rn(cy - hh, INV_SCALE), 0.0f), 1.0f);
    float x2 = fminf(fmaxf(__fmul_rn(cx + hw, INV_SCALE), 0.0f), 1.0f);
    float y2 = fminf(fmaxf(__fmul_rn(cy + hh, INV_SCALE), 0.0f), 1.0f);

    int i = b * NN + n;
    ((float4*)out)[i] = make_float4(x1, y1, x2, y2);     // boxes region [0, B*N*4)
    out[BB*NN*4 + i] = score;                            // scores
    out[BB*NN*5 + i] = (float)am;                        // cls_inds (as float)
    out[BB*NN*6 + i] = 0.0f;                             // keep default (NMS sets 1s)

    float off = __fmul_rn(2.0f, (float)am);
    g_offbox[i] = make_float4(x1 + off, y1 + off, x2 + off, y2 + off);
    g_score[i]  = score;

    // Append to per-(image,class) candidate list. Arrival order is irrelevant:
    // NMS sorts by the (score,index) key, so the result is deterministic.
    if (score > CONF_T) {
        int slot = atomicAdd(&g_cnt[b * NCLS + am], 1);
        if (slot < MAXC) g_cand[(b * NCLS + am) * MAXC + slot] = (short)n;
    }
}

// Fused GEMM (65536 x 512 x 25) + decode. 256 blocks x 256 threads, 1 pixel/thread
// (all blocks co-resident -> 148 SMs, 16 warps on doubled SMs for latency hiding).
__global__ __launch_bounds__(256, 2)
void k_gemm_decode(const float* __restrict__ feat,
                   const float* __restrict__ w_pred,
                   const float* __restrict__ b_pred,
                   float* __restrict__ out)
{
    __shared__ float w_s[CHUNK * OPAD];   // 28 KB
    __shared__ float b_s[OO];

    const int tid = threadIdx.x;
    const int b   = blockIdx.x >> 2;
    const int n0  = ((blockIdx.x & 3) << 8) | tid;
    const float* fp0 = feat + (size_t)b * CC * NN + n0;

    u64 acc[13];                          // channel pairs {2q, 2q+1}
    #pragma unroll
    for (int q = 0; q < 13; q++) acc[q] = 0ull;
    if (tid < OO) b_s[tid] = b_pred[tid];

    for (int half = 0; half < 2; half++) {
        __syncthreads();   // protect w_s from previous chunk's readers
        for (int i = tid; i < CHUNK * OPAD; i += 256) {
            int c = i / OPAD, o = i - c * OPAD;
            w_s[i] = (o < OO) ? w_pred[o * CC + half * CHUNK + c] : 0.0f;
        }
        __syncthreads();

        const float* fp = fp0 + (size_t)(half * CHUNK) * NN;
        #pragma unroll 4
        for (int cc = 0; cc < CHUNK; cc++) {
            float f = __ldg(fp + (size_t)cc * NN);
            u64 fA = pack2(f);
            const ulonglong2* wr = (const ulonglong2*)(w_s + cc * OPAD);
            #pragma unroll
            for (int j = 0; j < 7; j++) {
                ulonglong2 q = wr[j];           // one LDS.128 -> two channel pairs
                FMA2(acc[2*j], fA, q.x);
                if (2*j + 1 < 13) FMA2(acc[2*j + 1], fA, q.y);
            }
        }
    }

    float acc0[26];
    #pragma unroll
    for (int q = 0; q < 13; q++) unpack2(acc[q], acc0[2*q], acc0[2*q + 1]);
    decode_write(b, n0, acc0, b_s, out);
}

// NMS: one warp per (image, class) -> 1280 independent single-warp blocks.
// Class offset 2.0 makes cross-class IoU ~0 => per-class greedy is exactly
// equivalent to the reference's global sorted loop. Sub-threshold boxes can
// neither suppress nor be kept, so they were excluded at gather.
__global__ __launch_bounds__(32)
void k_nms(float* __restrict__ out)
{
    const int b    = blockIdx.x;
    const int c    = blockIdx.y;
    const int lane = threadIdx.x;
    const int idx  = b * NCLS + c;

    __shared__ u64    skey[MAXC];
    __shared__ float4 sb1[MAXC];
    __shared__ short  sn1[MAXC];
    __shared__ float4 sb2[MAXC];
    __shared__ short  sn2[MAXC];

    int cnt;
    if (lane == 0) { cnt = g_cnt[idx]; g_cnt[idx] = 0; }   // read + reset for next launch
    cnt = __shfl_sync(FULLM, cnt, 0);
    cnt = min(cnt, MAXC);
    if (cnt == 0) return;

    // Load candidates; key packs (score desc, pixel index asc) -> one u64 compare.
    // Keys are distinct (distinct n), so ranks form a permutation.
    for (int i = lane; i < cnt; i += 32) {
        int n = g_cand[idx * MAXC + i];
        float sc = g_score[b * NN + n];
        sb1[i] = g_offbox[b * NN + n];
        sn1[i] = (short)n;
        skey[i] = ((u64)__float_as_uint(sc) << 32) | (u64)(NN - 1 - n);
    }
    __syncwarp();

    // Rank sort (all-pairs), exactly matching jnp.argsort(-scores) stability.
    for (int i = lane; i < cnt; i += 32) {
        u64 ki = skey[i];
        int rank = 0;
        for (int j = 0; j < cnt; j++) rank += (skey[j] > ki);
        sb2[rank] = sb1[i];
        sn2[rank] = sn1[i];
    }
    __syncwarp();

    float* keep = out + (size_t)BB * NN * 6 + (size_t)b * NN;

    // Serial greedy over sorted order; 128-bit suppression mask lives in registers,
    // replicated uniformly across lanes via ballot -> uniform branches.
    unsigned s0 = 0, s1 = 0, s2 = 0, s3 = 0;
    for (int k = 0; k < cnt; k++) {
        unsigned sk = (k < 32) ? s0 : (k < 64) ? s1 : (k < 96) ? s2 : s3;
        if ((sk >> (k & 31)) & 1u) continue;      // suppressed (uniform)

        if (lane == 0) keep[sn2[k]] = 1.0f;
        float4 kb = sb2[k];
        float  ka = __fmul_rn(kb.z - kb.x, kb.w - kb.y);

        #pragma unroll
        for (int ch = 0; ch < 4; ch++) {
            int base = ch << 5;
            if (base >= cnt) break;               // uniform
            int j = base + lane;
            bool sup = false;
            if (j < cnt && j > k) {
                float4 ob = sb2[j];
                float xx1 = fmaxf(kb.x, ob.x);
                float yy1 = fmaxf(kb.y, ob.y);
                float xx2 = fminf(kb.z, ob.z);
                float yy2 = fminf(kb.w, ob.w);
                float w = fmaxf(EPS_IOU, xx2 - xx1);
                float h = fmaxf(EPS_IOU, yy2 - yy1);
                float inter = __fmul_rn(w, h);
                float oa = __fmul_rn(ob.z - ob.x, ob.w - ob.y);
                float iou = inter / (ka + oa - inter);
                sup = iou > NMS_T;
            }
            unsigned m = __ballot_sync(FULLM, sup);
            if      (ch == 0) s0 |= m;
            else if (ch == 1) s1 |= m;
            else if (ch == 2) s2 |= m;
            else              s3 |= m;
        }
    }
}

extern "C" void kernel_launch(void* const* d_in, const int* in_sizes, int n_in,
                              void* d_out, int out_size)
{
    const float* feat   = (const float*)d_in[0];
    const float* w_pred = (const float*)d_in[1];
    const float* b_pred = (const float*)d_in[2];
    float* out = (float*)d_out;

    k_gemm_decode<<<256, 256>>>(feat, w_pred, b_pred, out);
    k_nms<<<dim3(BB, NCLS), 32>>>(out);
}

// round 8
// speedup vs baseline: 2.3448x; 1.4734x over previous
#include <cuda_runtime.h>
#include <math.h>

// Problem constants
#define BB    64
#define CC    512
#define NN    1024          // 32*32 spatial
#define OO    25            // 1 conf + 20 cls + 4 box
#define OPAD  28            // pad to multiple of 4 for ulonglong2 smem loads
#define NCLS  20
#define CONF_T 0.01f
#define NMS_T  0.5f
#define EPS_IOU 1e-28f
#define INV_SCALE 0.0009765625f   // 1/1024
#define MAXC  128           // max candidates per (image,class); mean ~46
#define FULLM 0xffffffffu
#define PF    8             // feat prefetch depth (covers ~577cyc DRAM latency)

typedef unsigned long long u64;

// Scratch (allocation-free __device__ globals; g_cnt zeroed at load and re-zeroed
// by k_nms each launch -> graph-replay invariant).
__device__ float4 g_offbox[BB*NN];
__device__ float  g_score[BB*NN];
__device__ int    g_cnt[BB*NCLS];
__device__ short  g_cand[BB*NCLS*MAXC];

__device__ __forceinline__ float sigm(float x) { return 1.0f / (1.0f + expf(-x)); }

// packed f32x2 fma, lane-wise round-to-nearest (bitwise == scalar fmaf per lane)
#define FMA2(c, a, b) asm("fma.rn.f32x2 %0, %1, %2, %3;" : "=l"(c) : "l"(a), "l"(b), "l"(c))

__device__ __forceinline__ u64 pack2(float x) {
    u64 r; unsigned xb = __float_as_uint(x);
    asm("mov.b64 %0, {%1, %1};" : "=l"(r) : "r"(xb));
    return r;
}
__device__ __forceinline__ void unpack2(u64 v, float& lo, float& hi) {
    unsigned l, h;
    asm("mov.b64 {%0, %1}, %2;" : "=r"(l), "=r"(h) : "l"(v));
    lo = __uint_as_float(l); hi = __uint_as_float(h);
}

// Decode one pixel given its 25 raw logits (bias added here).
__device__ __forceinline__ void decode_write(int b, int n, const float* acc,
                                             const float* b_s, float* __restrict__ out)
{
    float p[OO];
    #pragma unroll
    for (int o = 0; o < OO; o++) p[o] = acc[o] + b_s[o];

    float conf = sigm(p[0]);

    // argmax over raw class logits (== argmax of softmax), first-max tie-break
    float m = p[1]; int am = 0;
    #pragma unroll
    for (int k = 1; k < NCLS; k++)
        if (p[1 + k] > m) { m = p[1 + k]; am = k; }

    float s = 0.0f;
    #pragma unroll
    for (int k = 0; k < NCLS; k++) s += expf(p[1 + k] - m);
    float score = conf / s;          // conf * max(softmax) == conf / sum(exp(l-m))

    float gx = (float)(n & 31), gy = (float)(n >> 5);
    float cx = (sigm(p[21]) + gx) * 32.0f;
    float cy = (sigm(p[22]) + gy) * 32.0f;
    float w  = expf(p[23]);
    float h  = expf(p[24]);
    float hw = __fmul_rn(w, 0.5f);
    float hh = __fmul_rn(h, 0.5f);
    float x1 = fminf(fmaxf(__fmul_rn(cx - hw, INV_SCALE), 0.0f), 1.0f);
    float y1 = fminf(fmaxf(__fmul_rn(cy - hh, INV_SCALE), 0.0f), 1.0f);
    float x2 = fminf(fmaxf(__fmul_rn(cx + hw, INV_SCALE), 0.0f), 1.0f);
    float y2 = fminf(fmaxf(__fmul_rn(cy + hh, INV_SCALE), 0.0f), 1.0f);

    int i = b * NN + n;
    ((float4*)out)[i] = make_float4(x1, y1, x2, y2);     // boxes region [0, B*N*4)
    out[BB*NN*4 + i] = score;                            // scores
    out[BB*NN*5 + i] = (float)am;                        // cls_inds (as float)
    out[BB*NN*6 + i] = 0.0f;                             // keep default (NMS sets 1s)

    float off = __fmul_rn(2.0f, (float)am);
    g_offbox[i] = make_float4(x1 + off, y1 + off, x2 + off, y2 + off);
    g_score[i]  = score;

    // Append to per-(image,class) candidate list. Arrival order is irrelevant:
    // NMS sorts by a (score,index) key, so the result is deterministic.
    if (score > CONF_T) {
        int slot = atomicAdd(&g_cnt[b * NCLS + am], 1);
        if (slot < MAXC) g_cand[(b * NCLS + am) * MAXC + slot] = (short)n;
    }
}

#define WSMEM_WORDS (CC * OPAD)                 // 14336 words = 56 KB
#define SMEM_BYTES  ((WSMEM_WORDS + 32) * 4)

// Fused GEMM (65536 x 512 x 25) + decode. 256 blocks x 128 threads, 2 px/thread.
// All 512 weight rows staged once in dynamic smem; feat loaded as float2 with an
// explicit 8-deep prefetch pipeline so DRAM latency (~577cyc) stays covered.
__global__ __launch_bounds__(128)
void k_gemm_decode(const float* __restrict__ feat,
                   const float* __restrict__ w_pred,
                   const float* __restrict__ b_pred,
                   float* __restrict__ out)
{
    extern __shared__ float smem_dyn[];
    float* w_s = smem_dyn;                      // CC x OPAD
    float* b_s = smem_dyn + WSMEM_WORDS;        // OO

    const int tid = threadIdx.x;
    const int b   = blockIdx.x >> 2;
    const int n0  = ((blockIdx.x & 3) << 8) | (tid << 1);
    const float2* fp = (const float2*)(feat + (size_t)b * CC * NN) + (n0 >> 1);

    // Stage all weights (padded rows -> ulonglong2-aligned channel pairs)
    for (int i = tid; i < WSMEM_WORDS; i += 128) {
        int c = i / OPAD, o = i - c * OPAD;
        w_s[i] = (o < OO) ? w_pred[o * CC + c] : 0.0f;
    }
    if (tid < OO) b_s[tid] = b_pred[tid];
    __syncthreads();

    u64 accA[13], accB[13];                     // channel pairs {2q,2q+1}, px0/px1
    #pragma unroll
    for (int q = 0; q < 13; q++) { accA[q] = 0ull; accB[q] = 0ull; }

    float2 buf[PF];
    #pragma unroll
    for (int k = 0; k < PF; k++) buf[k] = __ldg(fp + (size_t)k * (NN / 2));

    #pragma unroll 1
    for (int cc = 0; cc < CC - PF; cc += PF) {
        float2 cur[PF];
        #pragma unroll
        for (int k = 0; k < PF; k++) cur[k] = buf[k];
        #pragma unroll
        for (int k = 0; k < PF; k++)
            buf[k] = __ldg(fp + (size_t)(cc + PF + k) * (NN / 2));
        #pragma unroll
        for (int k = 0; k < PF; k++) {
            u64 fA = pack2(cur[k].x);
            u64 fB = pack2(cur[k].y);
            const ulonglong2* wr = (const ulonglong2*)(w_s + (cc + k) * OPAD);
            #pragma unroll
            for (int j = 0; j < 7; j++) {
                ulonglong2 q = wr[j];
                FMA2(accA[2*j], fA, q.x);
                FMA2(accB[2*j], fB, q.x);
                if (2*j + 1 < 13) { FMA2(accA[2*j+1], fA, q.y);
                                    FMA2(accB[2*j+1], fB, q.y); }
            }
        }
    }
    // epilogue: last PF channels from buf
    #pragma unroll
    for (int k = 0; k < PF; k++) {
        u64 fA = pack2(buf[k].x);
        u64 fB = pack2(buf[k].y);
        const ulonglong2* wr = (const ulonglong2*)(w_s + (CC - PF + k) * OPAD);
        #pragma unroll
        for (int j = 0; j < 7; j++) {
            ulonglong2 q = wr[j];
            FMA2(accA[2*j], fA, q.x);
            FMA2(accB[2*j], fB, q.x);
            if (2*j + 1 < 13) { FMA2(accA[2*j+1], fA, q.y);
                                FMA2(accB[2*j+1], fB, q.y); }
        }
    }

    float acc0[26], acc1[26];
    #pragma unroll
    for (int q = 0; q < 13; q++) {
        unpack2(accA[q], acc0[2*q], acc0[2*q+1]);
        unpack2(accB[q], acc1[2*q], acc1[2*q+1]);
    }
    decode_write(b, n0,     acc0, b_s, out);
    decode_write(b, n0 + 1, acc1, b_s, out);
}

__device__ __forceinline__ unsigned act_word(int cnt, int w) {
    int r = cnt - (w << 5);
    if (r <= 0) return 0u;
    if (r >= 32) return FULLM;
    return (1u << r) - 1u;
}

// NMS: one 128-thread block per (image, class). Class offset 2.0 makes cross-class
// IoU ~0 => per-class greedy == the reference's global sorted loop exactly.
// Phase 1 precomputes the full suppression bit-matrix in parallel (no serial
// dependencies -> pipelines at issue rate); phase 2 is a trivial register-mask walk.
__global__ __launch_bounds__(128)
void k_nms(float* __restrict__ out)
{
    const int b    = blockIdx.x;
    const int c    = blockIdx.y;
    const int idx  = b * NCLS + c;
    const int tid  = threadIdx.x;
    const int warp = tid >> 5;
    const int lane = tid & 31;

    __shared__ int    s_cnt;
    __shared__ u64    skey[MAXC];
    __shared__ float4 tbox[MAXC];
    __shared__ short  tn[MAXC];
    __shared__ float4 sbox[MAXC];
    __shared__ short  ssn[MAXC];
    __shared__ uint4  rows[MAXC];

    if (tid == 0) { int ct = g_cnt[idx]; g_cnt[idx] = 0; s_cnt = min(ct, MAXC); }
    __syncthreads();
    const int cnt = s_cnt;
    if (cnt == 0) return;

    // Load candidates; key = (score desc, pixel index asc) in one u64.
    if (tid < cnt) {
        int n = g_cand[idx * MAXC + tid];
        tbox[tid] = g_offbox[b * NN + n];
        tn[tid]   = (short)n;
        skey[tid] = ((u64)__float_as_uint(g_score[b * NN + n]) << 32)
                  | (u64)(NN - 1 - n);
    }
    __syncthreads();

    // Rank sort (keys distinct -> permutation), == jnp.argsort(-scores) stability.
    if (tid < cnt) {
        u64 ki = skey[tid];
        int rank = 0;
        for (int j = 0; j < cnt; j++) rank += (skey[j] > ki);
        sbox[rank] = tbox[tid];
        ssn[rank]  = tn[tid];
    }
    __syncthreads();

    // Phase 1: suppression matrix. Row i, bit j set iff j>i and IoU(i,j)>thresh.
    const int nch = (cnt + 31) >> 5;
    for (int i = warp; i < cnt; i += 4) {
        float4 kb = sbox[i];
        float  ka = __fmul_rn(kb.z - kb.x, kb.w - kb.y);
        unsigned w0 = 0, w1 = 0, w2 = 0, w3 = 0;
        for (int ch = 0; ch < nch; ch++) {
            int j = (ch << 5) + lane;
            bool sup = false;
            if (j < cnt && j > i) {
                float4 ob = sbox[j];
                float xx1 = fmaxf(kb.x, ob.x);
                float yy1 = fmaxf(kb.y, ob.y);
                float xx2 = fminf(kb.z, ob.z);
                float yy2 = fminf(kb.w, ob.w);
                float w = fmaxf(EPS_IOU, xx2 - xx1);
                float h = fmaxf(EPS_IOU, yy2 - yy1);
                float inter = __fmul_rn(w, h);
                float oa = __fmul_rn(ob.z - ob.x, ob.w - ob.y);
                float iou = inter / (ka + oa - inter);
                sup = iou > NMS_T;
            }
            unsigned m = __ballot_sync(FULLM, sup);
            if      (ch == 0) w0 = m;
            else if (ch == 1) w1 = m;
            else if (ch == 2) w2 = m;
            else              w3 = m;
        }
        if (lane == 0) rows[i] = make_uint4(w0, w1, w2, w3);
    }
    __syncthreads();

    // Phase 2: serial mask walk (warp 0, uniform; rows[k] load is act-independent
    // so it pipelines; chain is pure ALU ~10cyc/iter).
    if (warp == 0) {
        float* keep = out + (size_t)BB * NN * 6 + (size_t)b * NN;
        unsigned a0 = act_word(cnt, 0), a1 = act_word(cnt, 1);
        unsigned a2 = act_word(cnt, 2), a3 = act_word(cnt, 3);
        for (int k = 0; k < cnt; k++) {
            uint4 r = rows[k];
            unsigned aw = (k < 32) ? a0 : (k < 64) ? a1 : (k < 96) ? a2 : a3;
            if ((aw >> (k & 31)) & 1u) {
                if (lane == 0) keep[ssn[k]] = 1.0f;
                a0 &= ~r.x; a1 &= ~r.y; a2 &= ~r.z; a3 &= ~r.w;
            }
        }
    }
}

extern "C" void kernel_launch(void* const* d_in, const int* in_sizes, int n_in,
                              void* d_out, int out_size)
{
    const float* feat   = (const float*)d_in[0];
    const float* w_pred = (const float*)d_in[1];
    const float* b_pred = (const float*)d_in[2];
    float* out = (float*)d_out;

    static int smem_set = 0;
    if (!smem_set) {
        cudaFuncSetAttribute(k_gemm_decode,
                             cudaFuncAttributeMaxDynamicSharedMemorySize, SMEM_BYTES);
        smem_set = 1;
    }

    k_gemm_decode<<<256, 128, SMEM_BYTES>>>(feat, w_pred, b_pred, out);
    k_nms<<<dim3(BB, NCLS), 128>>>(out);
}